// round 9
// baseline (speedup 1.0000x reference)
#include <cuda_runtime.h>
#include <cuda_bf16.h>

// Problem constants (HungarianMatcher: B=16, Q=900, C=92, T=1600)
#define BQ   14400      // B*Q
#define NC   92         // num classes
#define NT   1600       // num targets

#define QT   48         // queries per block tile (14400 = 300*48)
#define THREADS 160     // threads per block; each owns 2 targets -> 320 t/block

// Scratch: softmax probabilities [BQ, NC]  (5.3 MB, static device array — no allocs)
__device__ float g_prob[BQ * NC];

// ---------------------------------------------------------------------------
// Kernel 1: row-wise softmax of pred_logits [BQ, NC] -> g_prob.
// Warp per row; 92 floats = 23 float4, lanes 0..22 own one float4 each.
// ---------------------------------------------------------------------------
__global__ void softmax_rows_kernel(const float* __restrict__ logits) {
    int row = blockIdx.x * (blockDim.x >> 5) + (threadIdx.x >> 5);
    if (row >= BQ) return;
    int lane = threadIdx.x & 31;
    bool act = lane < 23;

    const float4* in = reinterpret_cast<const float4*>(logits + (size_t)row * NC);
    float4 v = act ? in[lane] : make_float4(-1e30f, -1e30f, -1e30f, -1e30f);

    float m = fmaxf(fmaxf(v.x, v.y), fmaxf(v.z, v.w));
    #pragma unroll
    for (int o = 16; o; o >>= 1) m = fmaxf(m, __shfl_xor_sync(0xffffffffu, m, o));

    float4 e = make_float4(__expf(v.x - m), __expf(v.y - m),
                           __expf(v.z - m), __expf(v.w - m));
    float s = (e.x + e.y) + (e.z + e.w);
    #pragma unroll
    for (int o = 16; o; o >>= 1) s += __shfl_xor_sync(0xffffffffu, s, o);

    float r = __fdividef(1.0f, s);
    if (act) {
        float4* outp = reinterpret_cast<float4*>(g_prob + (size_t)row * NC);
        outp[lane] = make_float4(e.x * r, e.y * r, e.z * r, e.w * r);
    }
}

// ---------------------------------------------------------------------------
// Per-pair cost (proven math, rel_err 5e-8). Enclosing-box identity:
//   ew = (wp + wt) - iwu   (max(a,b)+min(a,b) = a+b)
// ---------------------------------------------------------------------------
__device__ __forceinline__ float pair_cost(
        float4 pc, float4 pxy, float area_p,
        float tx0, float ty0, float tx1, float ty1,
        float tcx, float tcy, float tw, float th,
        float area_t, float nprob) {
    float ax  = fmaxf(pxy.x, tx0);
    float bx  = fminf(pxy.z, tx1);
    float iwu = bx - ax;                       // unclamped intersection w
    float ay  = fmaxf(pxy.y, ty0);
    float by  = fminf(pxy.w, ty1);
    float ihu = by - ay;

    float iw = fmaxf(iwu, 0.0f);
    float ih = fmaxf(ihu, 0.0f);
    float inter = iw * ih;

    float ew  = (pc.z + tw) - iwu;             // enclosing w via identity
    float eh  = (pc.w + th) - ihu;
    float enc = ew * eh;

    float uni = (area_p + area_t) - inter;
    float emu = enc - uni;
    float num = fmaf(inter, enc, -emu * uni);  // inter*enc - (enc-uni)*uni
    float giou = __fdividef(num, uni * enc);

    float cb = fabsf(pc.x - tcx) + fabsf(pc.y - tcy)
             + fabsf(pc.z - tw)  + fabsf(pc.w - th);

    return fmaf(5.0f, cb, fmaf(-2.0f, giou, nprob));
}

// ---------------------------------------------------------------------------
// Kernel 2: pair cost, q-tiled, dual-target threads.
// grid = (NT/(2*THREADS) = 5, BQ/QT = 300) = 1500 blocks = 1.014 waves at
// 10 blocks/SM. NO min-blocks hint: regs must stay at ~40 for ILP (R7/R8
// both showed reg-capping to 32 collapses issue rate).
// ---------------------------------------------------------------------------
__global__ __launch_bounds__(THREADS) void cost_kernel(
        const float* __restrict__ pred_boxes,   // [BQ,4] cxcywh
        const int*   __restrict__ tgt_labels,   // [NT] int32
        const float* __restrict__ tgt_boxes,    // [NT,4] cxcywh
        float*       __restrict__ out) {
    __shared__ float4 s_xy[QT];            // pred xyxy
    __shared__ float4 s_cw[QT];            // pred cxcywh
    __shared__ float  s_prob[QT * NC];     // softmax rows for this q-tile

    const int tid = threadIdx.x;
    const int q0  = blockIdx.y * QT;

    // float4 fill of the probability tile: 48*92 = 4416 floats = 1104 float4.
    // Tile base offset q0*NC floats = blockIdx.y*17664 bytes -> 16B aligned.
    {
        const float4* gp4 = reinterpret_cast<const float4*>(g_prob + (size_t)q0 * NC);
        float4* sp4 = reinterpret_cast<float4*>(s_prob);
        #pragma unroll
        for (int i = tid; i < (QT * NC) / 4; i += THREADS) sp4[i] = gp4[i];
    }

    if (tid < QT) {
        float4 b = reinterpret_cast<const float4*>(pred_boxes)[q0 + tid];
        s_cw[tid] = b;
        s_xy[tid] = make_float4(b.x - 0.5f * b.z, b.y - 0.5f * b.w,
                                b.x + 0.5f * b.z, b.y + 0.5f * b.w);
    }
    __syncthreads();

    // Two adjacent targets per thread, loaded once.
    const int t0 = blockIdx.x * (2 * THREADS) + 2 * tid;
    float4 ta = reinterpret_cast<const float4*>(tgt_boxes)[t0];
    float4 tb = reinterpret_cast<const float4*>(tgt_boxes)[t0 + 1];
    int la = min(max(tgt_labels[t0],     0), NC - 1);
    int lb = min(max(tgt_labels[t0 + 1], 0), NC - 1);

    const float ax0 = ta.x - 0.5f * ta.z, ay0 = ta.y - 0.5f * ta.w;
    const float ax1 = ta.x + 0.5f * ta.z, ay1 = ta.y + 0.5f * ta.w;
    const float areaA = ta.z * ta.w;

    const float bx0 = tb.x - 0.5f * tb.z, by0 = tb.y - 0.5f * tb.w;
    const float bx1 = tb.x + 0.5f * tb.z, by1 = tb.y + 0.5f * tb.w;
    const float areaB = tb.z * tb.w;

    float2* outp = reinterpret_cast<float2*>(out + (size_t)q0 * NT + t0);

    #pragma unroll 6
    for (int j = 0; j < QT; j++) {
        float4 pxy = s_xy[j];              // warp-uniform LDS.128 broadcast
        float4 pc  = s_cw[j];
        float  area_p = pc.z * pc.w;       // shared by both pairs
        const float* pr = s_prob + j * NC;

        float c0 = pair_cost(pc, pxy, area_p, ax0, ay0, ax1, ay1,
                             ta.x, ta.y, ta.z, ta.w, areaA, -pr[la]);
        float c1 = pair_cost(pc, pxy, area_p, bx0, by0, bx1, by1,
                             tb.x, tb.y, tb.z, tb.w, areaB, -pr[lb]);

        outp[(size_t)j * (NT / 2)] = make_float2(c0, c1);
    }
}

// ---------------------------------------------------------------------------
extern "C" void kernel_launch(void* const* d_in, const int* in_sizes, int n_in,
                              void* d_out, int out_size) {
    const float* pred_logits = (const float*)d_in[0];  // [16,900,92]
    const float* pred_boxes  = (const float*)d_in[1];  // [16,900,4]
    const int*   tgt_labels  = (const int*)  d_in[2];  // [1600] int32
    const float* tgt_boxes   = (const float*)d_in[3];  // [1600,4]
    float*       out         = (float*)d_out;          // [16,900,1600]

    (void)in_sizes; (void)n_in; (void)out_size;

    // Kernel 1: softmax rows. 8 warps/block -> 1800 blocks.
    {
        int warps_per_block = 8;
        int threads = warps_per_block * 32;
        int blocks  = (BQ + warps_per_block - 1) / warps_per_block;
        softmax_rows_kernel<<<blocks, threads>>>(pred_logits);
    }

    // Kernel 2: pair costs. grid (5, 300), 160 threads, 2 targets/thread.
    {
        dim3 block(THREADS, 1, 1);
        dim3 grid(NT / (2 * THREADS), BQ / QT, 1);
        cost_kernel<<<grid, block>>>(pred_boxes, tgt_labels, tgt_boxes, out);
    }
}

// round 10
// speedup vs baseline: 1.5272x; 1.5272x over previous
#include <cuda_runtime.h>
#include <cuda_bf16.h>

// Problem constants (HungarianMatcher: B=16, Q=900, C=92, T=1600)
#define BQ   14400      // B*Q
#define NC   92         // num classes
#define NT   1600       // num targets

#define QT   36         // queries per block tile (14400 = 400*36)
#define THREADS 160     // threads per block; each owns 2 targets -> 320 t/block

// Scratch: softmax probabilities [BQ, NC]  (5.3 MB, static device array — no allocs)
__device__ float g_prob[BQ * NC];

// ---------------------------------------------------------------------------
// Kernel 1: row-wise softmax of pred_logits [BQ, NC] -> g_prob.
// Warp per row; 92 floats = 23 float4, lanes 0..22 own one float4 each.
// ---------------------------------------------------------------------------
__global__ void softmax_rows_kernel(const float* __restrict__ logits) {
    int row = blockIdx.x * (blockDim.x >> 5) + (threadIdx.x >> 5);
    if (row >= BQ) return;
    int lane = threadIdx.x & 31;
    bool act = lane < 23;

    const float4* in = reinterpret_cast<const float4*>(logits + (size_t)row * NC);
    float4 v = act ? in[lane] : make_float4(-1e30f, -1e30f, -1e30f, -1e30f);

    float m = fmaxf(fmaxf(v.x, v.y), fmaxf(v.z, v.w));
    #pragma unroll
    for (int o = 16; o; o >>= 1) m = fmaxf(m, __shfl_xor_sync(0xffffffffu, m, o));

    float4 e = make_float4(__expf(v.x - m), __expf(v.y - m),
                           __expf(v.z - m), __expf(v.w - m));
    float s = (e.x + e.y) + (e.z + e.w);
    #pragma unroll
    for (int o = 16; o; o >>= 1) s += __shfl_xor_sync(0xffffffffu, s, o);

    float r = __fdividef(1.0f, s);
    if (act) {
        float4* outp = reinterpret_cast<float4*>(g_prob + (size_t)row * NC);
        outp[lane] = make_float4(e.x * r, e.y * r, e.z * r, e.w * r);
    }
}

// ---------------------------------------------------------------------------
// Per-pair cost (proven math, rel_err 5e-8). Enclosing-box identity:
//   ew = (wp + wt) - iwu   (max(a,b)+min(a,b) = a+b)
// ---------------------------------------------------------------------------
__device__ __forceinline__ float pair_cost(
        float4 pc, float4 pxy, float area_p,
        float tx0, float ty0, float tx1, float ty1,
        float tcx, float tcy, float tw, float th,
        float area_t, float nprob) {
    float ax  = fmaxf(pxy.x, tx0);
    float bx  = fminf(pxy.z, tx1);
    float iwu = bx - ax;                       // unclamped intersection w
    float ay  = fmaxf(pxy.y, ty0);
    float by  = fminf(pxy.w, ty1);
    float ihu = by - ay;

    float iw = fmaxf(iwu, 0.0f);
    float ih = fmaxf(ihu, 0.0f);
    float inter = iw * ih;

    float ew  = (pc.z + tw) - iwu;             // enclosing w via identity
    float eh  = (pc.w + th) - ihu;
    float enc = ew * eh;

    float uni = (area_p + area_t) - inter;
    float emu = enc - uni;
    float num = fmaf(inter, enc, -emu * uni);  // inter*enc - (enc-uni)*uni
    float giou = __fdividef(num, uni * enc);

    float cb = fabsf(pc.x - tcx) + fabsf(pc.y - tcy)
             + fabsf(pc.z - tw)  + fabsf(pc.w - th);

    return fmaf(5.0f, cb, fmaf(-2.0f, giou, nprob));
}

// ---------------------------------------------------------------------------
// Kernel 2 (exact R4 config — best measured: 33.3 us): pair cost, q-tiled,
// dual-target threads. grid = (5, 400), block = 160, natural regs (~40).
// NO min-blocks hint (R7/R8: reg-capping collapses issue rate).
// Occupancy is unlocked host-side via the shared-memory carveout attribute.
// ---------------------------------------------------------------------------
__global__ __launch_bounds__(THREADS) void cost_kernel(
        const float* __restrict__ pred_boxes,   // [BQ,4] cxcywh
        const int*   __restrict__ tgt_labels,   // [NT] int32
        const float* __restrict__ tgt_boxes,    // [NT,4] cxcywh
        float*       __restrict__ out) {
    __shared__ float4 s_xy[QT];            // pred xyxy
    __shared__ float4 s_cw[QT];            // pred cxcywh
    __shared__ float  s_prob[QT * NC];     // softmax rows for this q-tile

    const int tid = threadIdx.x;
    const int q0  = blockIdx.y * QT;

    // float4 fill of the probability tile: 36*92 = 3312 floats = 828 float4.
    {
        const float4* gp4 = reinterpret_cast<const float4*>(g_prob + (size_t)q0 * NC);
        float4* sp4 = reinterpret_cast<float4*>(s_prob);
        #pragma unroll
        for (int i = tid; i < (QT * NC) / 4; i += THREADS) sp4[i] = gp4[i];
    }

    if (tid < QT) {
        float4 b = reinterpret_cast<const float4*>(pred_boxes)[q0 + tid];
        s_cw[tid] = b;
        s_xy[tid] = make_float4(b.x - 0.5f * b.z, b.y - 0.5f * b.w,
                                b.x + 0.5f * b.z, b.y + 0.5f * b.w);
    }
    __syncthreads();

    // Two adjacent targets per thread, loaded once.
    const int t0 = blockIdx.x * (2 * THREADS) + 2 * tid;
    float4 ta = reinterpret_cast<const float4*>(tgt_boxes)[t0];
    float4 tb = reinterpret_cast<const float4*>(tgt_boxes)[t0 + 1];
    int la = min(max(tgt_labels[t0],     0), NC - 1);
    int lb = min(max(tgt_labels[t0 + 1], 0), NC - 1);

    const float ax0 = ta.x - 0.5f * ta.z, ay0 = ta.y - 0.5f * ta.w;
    const float ax1 = ta.x + 0.5f * ta.z, ay1 = ta.y + 0.5f * ta.w;
    const float areaA = ta.z * ta.w;

    const float bx0 = tb.x - 0.5f * tb.z, by0 = tb.y - 0.5f * tb.w;
    const float bx1 = tb.x + 0.5f * tb.z, by1 = tb.y + 0.5f * tb.w;
    const float areaB = tb.z * tb.w;

    float2* outp = reinterpret_cast<float2*>(out + (size_t)q0 * NT + t0);

    #pragma unroll 6
    for (int j = 0; j < QT; j++) {
        float4 pxy = s_xy[j];              // warp-uniform LDS.128 broadcast
        float4 pc  = s_cw[j];
        float  area_p = pc.z * pc.w;       // shared by both pairs
        const float* pr = s_prob + j * NC;

        float c0 = pair_cost(pc, pxy, area_p, ax0, ay0, ax1, ay1,
                             ta.x, ta.y, ta.z, ta.w, areaA, -pr[la]);
        float c1 = pair_cost(pc, pxy, area_p, bx0, by0, bx1, by1,
                             tb.x, tb.y, tb.z, tb.w, areaB, -pr[lb]);

        outp[(size_t)j * (NT / 2)] = make_float2(c0, c1);
    }
}

// ---------------------------------------------------------------------------
extern "C" void kernel_launch(void* const* d_in, const int* in_sizes, int n_in,
                              void* d_out, int out_size) {
    const float* pred_logits = (const float*)d_in[0];  // [16,900,92]
    const float* pred_boxes  = (const float*)d_in[1];  // [16,900,4]
    const int*   tgt_labels  = (const int*)  d_in[2];  // [1600] int32
    const float* tgt_boxes   = (const float*)d_in[3];  // [1600,4]
    float*       out         = (float*)d_out;          // [16,900,1600]

    (void)in_sizes; (void)n_in; (void)out_size;

    // Unlock L1/shared carveout so ~10 blocks (not ~6) fit per SM.
    // Host-side attribute set: no allocation, no sync, capture-safe,
    // deterministic (same call every invocation).
    cudaFuncSetAttribute(cost_kernel,
                         cudaFuncAttributePreferredSharedMemoryCarveout, 100);

    // Kernel 1: softmax rows. 8 warps/block -> 1800 blocks.
    {
        int warps_per_block = 8;
        int threads = warps_per_block * 32;
        int blocks  = (BQ + warps_per_block - 1) / warps_per_block;
        softmax_rows_kernel<<<blocks, threads>>>(pred_logits);
    }

    // Kernel 2: pair costs. grid (5, 400), 160 threads, 2 targets/thread.
    {
        dim3 block(THREADS, 1, 1);
        dim3 grid(NT / (2 * THREADS), BQ / QT, 1);
        cost_kernel<<<grid, block>>>(pred_boxes, tgt_labels, tgt_boxes, out);
    }
}

// round 11
// speedup vs baseline: 1.6096x; 1.0539x over previous
#include <cuda_runtime.h>
#include <cuda_fp16.h>
#include <cuda_bf16.h>

// Problem constants (HungarianMatcher: B=16, Q=900, C=92, T=1600)
#define BQ   14400      // B*Q
#define NC   92         // num classes
#define NT   1600       // num targets

#define QT   45         // queries per block tile (14400 = 320*45)
#define THREADS 160     // threads per block; each owns 2 targets -> 320 t/block

// Scratch: softmax probabilities [BQ, NC] in fp16 (2.65 MB, static device array)
__device__ __half g_prob[BQ * NC];

// ---------------------------------------------------------------------------
// Kernel 1: row-wise softmax of pred_logits [BQ, NC] -> g_prob (fp16).
// Warp per row; 92 floats = 23 float4, lanes 0..22 own one float4 each.
// Each active lane writes its 4 probs as 2 half2 (one 8B store, 8B-aligned:
// row base = row*184 bytes, lane offset = lane*8).
// ---------------------------------------------------------------------------
__global__ void softmax_rows_kernel(const float* __restrict__ logits) {
    int row = blockIdx.x * (blockDim.x >> 5) + (threadIdx.x >> 5);
    if (row >= BQ) return;
    int lane = threadIdx.x & 31;
    bool act = lane < 23;

    const float4* in = reinterpret_cast<const float4*>(logits + (size_t)row * NC);
    float4 v = act ? in[lane] : make_float4(-1e30f, -1e30f, -1e30f, -1e30f);

    float m = fmaxf(fmaxf(v.x, v.y), fmaxf(v.z, v.w));
    #pragma unroll
    for (int o = 16; o; o >>= 1) m = fmaxf(m, __shfl_xor_sync(0xffffffffu, m, o));

    float4 e = make_float4(__expf(v.x - m), __expf(v.y - m),
                           __expf(v.z - m), __expf(v.w - m));
    float s = (e.x + e.y) + (e.z + e.w);
    #pragma unroll
    for (int o = 16; o; o >>= 1) s += __shfl_xor_sync(0xffffffffu, s, o);

    float r = __fdividef(1.0f, s);
    if (act) {
        __half2 h0 = __floats2half2_rn(e.x * r, e.y * r);
        __half2 h1 = __floats2half2_rn(e.z * r, e.w * r);
        __half2* outp = reinterpret_cast<__half2*>(g_prob + (size_t)row * NC);
        outp[2 * lane]     = h0;
        outp[2 * lane + 1] = h1;
    }
}

// ---------------------------------------------------------------------------
// Per-pair cost (proven math, rel_err 5e-8 in fp32). Enclosing-box identity:
//   ew = (wp + wt) - iwu   (max(a,b)+min(a,b) = a+b)
// ---------------------------------------------------------------------------
__device__ __forceinline__ float pair_cost(
        float4 pc, float4 pxy, float area_p,
        float tx0, float ty0, float tx1, float ty1,
        float tcx, float tcy, float tw, float th,
        float area_t, float nprob) {
    float ax  = fmaxf(pxy.x, tx0);
    float bx  = fminf(pxy.z, tx1);
    float iwu = bx - ax;                       // unclamped intersection w
    float ay  = fmaxf(pxy.y, ty0);
    float by  = fminf(pxy.w, ty1);
    float ihu = by - ay;

    float iw = fmaxf(iwu, 0.0f);
    float ih = fmaxf(ihu, 0.0f);
    float inter = iw * ih;

    float ew  = (pc.z + tw) - iwu;             // enclosing w via identity
    float eh  = (pc.w + th) - ihu;
    float enc = ew * eh;

    float uni = (area_p + area_t) - inter;
    float emu = enc - uni;
    float num = fmaf(inter, enc, -emu * uni);  // inter*enc - (enc-uni)*uni
    float giou = __fdividef(num, uni * enc);

    float cb = fabsf(pc.x - tcx) + fabsf(pc.y - tcy)
             + fabsf(pc.z - tw)  + fabsf(pc.w - th);

    return fmaf(5.0f, cb, fmaf(-2.0f, giou, nprob));
}

// ---------------------------------------------------------------------------
// Kernel 2: pair cost, q-tiled, dual-target threads, fp16 prob tile.
// grid = (5, 320) = 1600 blocks = 1.08 waves at 10 blocks/SM.
// smem ~9.7 KB/block -> smem budget (~100 KB eff.) fits 10 blocks; regs
// (natural ~40, NO min-blocks hint) also allow 10 -> 50 warps resident.
// ---------------------------------------------------------------------------
__global__ __launch_bounds__(THREADS) void cost_kernel(
        const float* __restrict__ pred_boxes,   // [BQ,4] cxcywh
        const int*   __restrict__ tgt_labels,   // [NT] int32
        const float* __restrict__ tgt_boxes,    // [NT,4] cxcywh
        float*       __restrict__ out) {
    __shared__ float4 s_xy[QT];            // pred xyxy
    __shared__ float4 s_cw[QT];            // pred cxcywh
    __shared__ __half s_prob[QT * NC];     // fp16 softmax rows (8.3 KB)

    const int tid = threadIdx.x;
    const int q0  = blockIdx.y * QT;

    // Fill prob tile: 45*92 = 4140 halves = 8280 B = 1035 x 8B (tile base is
    // blockIdx.y*8280 bytes -> 8B aligned; uint2 copies are legal).
    {
        const uint2* gp2 = reinterpret_cast<const uint2*>(g_prob + (size_t)q0 * NC);
        uint2* sp2 = reinterpret_cast<uint2*>(s_prob);
        #pragma unroll
        for (int i = tid; i < (QT * NC) / 4; i += THREADS) sp2[i] = gp2[i];
    }

    if (tid < QT) {
        float4 b = reinterpret_cast<const float4*>(pred_boxes)[q0 + tid];
        s_cw[tid] = b;
        s_xy[tid] = make_float4(b.x - 0.5f * b.z, b.y - 0.5f * b.w,
                                b.x + 0.5f * b.z, b.y + 0.5f * b.w);
    }
    __syncthreads();

    // Two adjacent targets per thread, loaded once.
    const int t0 = blockIdx.x * (2 * THREADS) + 2 * tid;
    float4 ta = reinterpret_cast<const float4*>(tgt_boxes)[t0];
    float4 tb = reinterpret_cast<const float4*>(tgt_boxes)[t0 + 1];
    int la = min(max(tgt_labels[t0],     0), NC - 1);
    int lb = min(max(tgt_labels[t0 + 1], 0), NC - 1);

    const float ax0 = ta.x - 0.5f * ta.z, ay0 = ta.y - 0.5f * ta.w;
    const float ax1 = ta.x + 0.5f * ta.z, ay1 = ta.y + 0.5f * ta.w;
    const float areaA = ta.z * ta.w;

    const float bx0 = tb.x - 0.5f * tb.z, by0 = tb.y - 0.5f * tb.w;
    const float bx1 = tb.x + 0.5f * tb.z, by1 = tb.y + 0.5f * tb.w;
    const float areaB = tb.z * tb.w;

    float2* outp = reinterpret_cast<float2*>(out + (size_t)q0 * NT + t0);

    #pragma unroll 5
    for (int j = 0; j < QT; j++) {
        float4 pxy = s_xy[j];              // warp-uniform LDS.128 broadcast
        float4 pc  = s_cw[j];
        float  area_p = pc.z * pc.w;       // shared by both pairs
        const __half* pr = s_prob + j * NC;

        float npa = -__half2float(pr[la]);
        float npb = -__half2float(pr[lb]);

        float c0 = pair_cost(pc, pxy, area_p, ax0, ay0, ax1, ay1,
                             ta.x, ta.y, ta.z, ta.w, areaA, npa);
        float c1 = pair_cost(pc, pxy, area_p, bx0, by0, bx1, by1,
                             tb.x, tb.y, tb.z, tb.w, areaB, npb);

        outp[(size_t)j * (NT / 2)] = make_float2(c0, c1);
    }
}

// ---------------------------------------------------------------------------
extern "C" void kernel_launch(void* const* d_in, const int* in_sizes, int n_in,
                              void* d_out, int out_size) {
    const float* pred_logits = (const float*)d_in[0];  // [16,900,92]
    const float* pred_boxes  = (const float*)d_in[1];  // [16,900,4]
    const int*   tgt_labels  = (const int*)  d_in[2];  // [1600] int32
    const float* tgt_boxes   = (const float*)d_in[3];  // [1600,4]
    float*       out         = (float*)d_out;          // [16,900,1600]

    (void)in_sizes; (void)n_in; (void)out_size;

    // Kernel 1: softmax rows. 8 warps/block -> 1800 blocks.
    {
        int warps_per_block = 8;
        int threads = warps_per_block * 32;
        int blocks  = (BQ + warps_per_block - 1) / warps_per_block;
        softmax_rows_kernel<<<blocks, threads>>>(pred_logits);
    }

    // Kernel 2: pair costs. grid (5, 320), 160 threads, 2 targets/thread.
    {
        dim3 block(THREADS, 1, 1);
        dim3 grid(NT / (2 * THREADS), BQ / QT, 1);
        cost_kernel<<<grid, block>>>(pred_boxes, tgt_labels, tgt_boxes, out);
    }
}

// round 13
// speedup vs baseline: 1.6277x; 1.0113x over previous
#include <cuda_runtime.h>
#include <cuda_fp16.h>
#include <cuda_bf16.h>

// Problem constants (HungarianMatcher: B=16, Q=900, C=92, T=1600)
#define BQ   14400      // B*Q
#define NC   92         // num classes
#define NT   1600       // num targets

#define QT   45         // queries per block tile (14400 = 320*45)
#define THREADS 160     // threads per block; each owns 2 targets -> 320 t/block

// Scratch: softmax probabilities [BQ, NC] in fp16 (2.65 MB, static device array)
__device__ __half g_prob[BQ * NC];

// ---------------------------------------------------------------------------
// Kernel 1: row-wise softmax of pred_logits [BQ, NC] -> g_prob (fp16).
// Warp per row; 92 floats = 23 float4, lanes 0..22 own one float4 each.
// ---------------------------------------------------------------------------
__global__ void softmax_rows_kernel(const float* __restrict__ logits) {
    int row = blockIdx.x * (blockDim.x >> 5) + (threadIdx.x >> 5);
    if (row >= BQ) return;
    int lane = threadIdx.x & 31;
    bool act = lane < 23;

    const float4* in = reinterpret_cast<const float4*>(logits + (size_t)row * NC);
    float4 v = act ? in[lane] : make_float4(-1e30f, -1e30f, -1e30f, -1e30f);

    float m = fmaxf(fmaxf(v.x, v.y), fmaxf(v.z, v.w));
    #pragma unroll
    for (int o = 16; o; o >>= 1) m = fmaxf(m, __shfl_xor_sync(0xffffffffu, m, o));

    float4 e = make_float4(__expf(v.x - m), __expf(v.y - m),
                           __expf(v.z - m), __expf(v.w - m));
    float s = (e.x + e.y) + (e.z + e.w);
    #pragma unroll
    for (int o = 16; o; o >>= 1) s += __shfl_xor_sync(0xffffffffu, s, o);

    float r = __fdividef(1.0f, s);
    if (act) {
        __half2 h0 = __floats2half2_rn(e.x * r, e.y * r);
        __half2 h1 = __floats2half2_rn(e.z * r, e.w * r);
        __half2* outp = reinterpret_cast<__half2*>(g_prob + (size_t)row * NC);
        outp[2 * lane]     = h0;
        outp[2 * lane + 1] = h1;
    }
}

// helper: reinterpret 32-bit word <-> half2
__device__ __forceinline__ __half2 u2h(unsigned u) {
    __half2 h; *reinterpret_cast<unsigned*>(&h) = u; return h;
}

// ---------------------------------------------------------------------------
// fp32 GIoU for one pair (proven R4/R11 math, rel_err 5e-8).
// Enclosing-box identity: ew = (wp + wt) - iwu.
// ---------------------------------------------------------------------------
__device__ __forceinline__ float giou_pair(
        float4 pxy, float pcz, float pcw, float area_p,
        float tx0, float ty0, float tx1, float ty1,
        float tw, float th, float area_t) {
    float iwu = fminf(pxy.z, tx1) - fmaxf(pxy.x, tx0);
    float ihu = fminf(pxy.w, ty1) - fmaxf(pxy.y, ty0);

    float iw = fmaxf(iwu, 0.0f);
    float ih = fmaxf(ihu, 0.0f);
    float inter = iw * ih;

    float ew  = (pcz + tw) - iwu;
    float eh  = (pcw + th) - ihu;
    float enc = ew * eh;

    float uni = (area_p + area_t) - inter;
    float emu = enc - uni;
    float num = fmaf(inter, enc, -emu * uni);
    return __fdividef(num, uni * enc);
}

// ---------------------------------------------------------------------------
// Kernel 2: pair cost, q-tiled, dual-target threads.
// GIoU in fp32 (precision-critical ratios); L1 box cost packed fp16x2 across
// the two targets (coords in [0,1], well-conditioned -> quantization only).
// grid = (5, 320) = 1600 blocks, 160 threads. No min-blocks hints (regs free).
// ---------------------------------------------------------------------------
__global__ __launch_bounds__(THREADS) void cost_kernel(
        const float* __restrict__ pred_boxes,   // [BQ,4] cxcywh
        const int*   __restrict__ tgt_labels,   // [NT] int32
        const float* __restrict__ tgt_boxes,    // [NT,4] cxcywh
        float*       __restrict__ out) {
    __shared__ float4 s_xy[QT];            // pred xyxy (fp32)
    __shared__ float4 s_cz[QT];            // {pcz, pcw, area_p, pad} (fp32)
    __shared__ __align__(16) uint4 s_ch[QT]; // 4 dup'd half2: pcx,pcy,pcz,pcw
    __shared__ __half s_prob[QT * NC];     // fp16 softmax rows (8.3 KB)

    const int tid = threadIdx.x;
    const int q0  = blockIdx.y * QT;

    // Fill prob tile: 45*92 = 4140 halves = 8280 B = 1035 x 8B chunks.
    {
        const uint2* gp2 = reinterpret_cast<const uint2*>(g_prob + (size_t)q0 * NC);
        uint2* sp2 = reinterpret_cast<uint2*>(s_prob);
        #pragma unroll
        for (int i = tid; i < (QT * NC) / 4; i += THREADS) sp2[i] = gp2[i];
    }

    if (tid < QT) {
        float4 b = reinterpret_cast<const float4*>(pred_boxes)[q0 + tid];
        s_xy[tid] = make_float4(b.x - 0.5f * b.z, b.y - 0.5f * b.w,
                                b.x + 0.5f * b.z, b.y + 0.5f * b.w);
        s_cz[tid] = make_float4(b.z, b.w, b.z * b.w, 0.0f);
        __half2 hx = __float2half2_rn(b.x);
        __half2 hy = __float2half2_rn(b.y);
        __half2 hz = __float2half2_rn(b.z);
        __half2 hw = __float2half2_rn(b.w);
        s_ch[tid] = make_uint4(*reinterpret_cast<unsigned*>(&hx),
                               *reinterpret_cast<unsigned*>(&hy),
                               *reinterpret_cast<unsigned*>(&hz),
                               *reinterpret_cast<unsigned*>(&hw));
    }
    __syncthreads();

    // Two adjacent targets per thread, loaded once.
    const int t0 = blockIdx.x * (2 * THREADS) + 2 * tid;
    float4 ta = reinterpret_cast<const float4*>(tgt_boxes)[t0];
    float4 tb = reinterpret_cast<const float4*>(tgt_boxes)[t0 + 1];
    int la = min(max(tgt_labels[t0],     0), NC - 1);
    int lb = min(max(tgt_labels[t0 + 1], 0), NC - 1);

    // fp32 target xyxy + areas (GIoU side)
    const float ax0 = ta.x - 0.5f * ta.z, ay0 = ta.y - 0.5f * ta.w;
    const float ax1 = ta.x + 0.5f * ta.z, ay1 = ta.y + 0.5f * ta.w;
    const float areaA = ta.z * ta.w;
    const float bx0 = tb.x - 0.5f * tb.z, by0 = tb.y - 0.5f * tb.w;
    const float bx1 = tb.x + 0.5f * tb.z, by1 = tb.y + 0.5f * tb.w;
    const float areaB = tb.z * tb.w;

    // fp16 packed target cxcywh (L1 side): lo = target a, hi = target b
    const __half2 tcx2 = __floats2half2_rn(ta.x, tb.x);
    const __half2 tcy2 = __floats2half2_rn(ta.y, tb.y);
    const __half2 tw2  = __floats2half2_rn(ta.z, tb.z);
    const __half2 th2  = __floats2half2_rn(ta.w, tb.w);

    float2* outp = reinterpret_cast<float2*>(out + (size_t)q0 * NT + t0);

    #pragma unroll 5
    for (int j = 0; j < QT; j++) {
        float4 pxy = s_xy[j];              // warp-uniform LDS.128 broadcasts
        float4 pz  = s_cz[j];
        uint4  H   = s_ch[j];

        // L1 box cost, packed over both targets (fp16x2)
        __half2 d0 = __habs2(__hsub2(u2h(H.x), tcx2));
        __half2 d1 = __habs2(__hsub2(u2h(H.y), tcy2));
        __half2 d2 = __habs2(__hsub2(u2h(H.z), tw2));
        __half2 d3 = __habs2(__hsub2(u2h(H.w), th2));
        float2 cb = __half22float2(__hadd2(__hadd2(d0, d1), __hadd2(d2, d3)));

        // GIoU fp32 per pair
        float ga = giou_pair(pxy, pz.x, pz.y, pz.z,
                             ax0, ay0, ax1, ay1, ta.z, ta.w, areaA);
        float gb = giou_pair(pxy, pz.x, pz.y, pz.z,
                             bx0, by0, bx1, by1, tb.z, tb.w, areaB);

        // class cost: -prob[q][label]
        const __half* pr = s_prob + j * NC;
        float npa = -__half2float(pr[la]);
        float npb = -__half2float(pr[lb]);

        float c0 = fmaf(5.0f, cb.x, fmaf(-2.0f, ga, npa));
        float c1 = fmaf(5.0f, cb.y, fmaf(-2.0f, gb, npb));

        outp[(size_t)j * (NT / 2)] = make_float2(c0, c1);
    }
}

// ---------------------------------------------------------------------------
extern "C" void kernel_launch(void* const* d_in, const int* in_sizes, int n_in,
                              void* d_out, int out_size) {
    const float* pred_logits = (const float*)d_in[0];  // [16,900,92]
    const float* pred_boxes  = (const float*)d_in[1];  // [16,900,4]
    const int*   tgt_labels  = (const int*)  d_in[2];  // [1600] int32
    const float* tgt_boxes   = (const float*)d_in[3];  // [1600,4]
    float*       out         = (float*)d_out;          // [16,900,1600]

    (void)in_sizes; (void)n_in; (void)out_size;

    // Kernel 1: softmax rows. 8 warps/block -> 1800 blocks.
    {
        int warps_per_block = 8;
        int threads = warps_per_block * 32;
        int blocks  = (BQ + warps_per_block - 1) / warps_per_block;
        softmax_rows_kernel<<<blocks, threads>>>(pred_logits);
    }

    // Kernel 2: pair costs. grid (5, 320), 160 threads, 2 targets/thread.
    {
        dim3 block(THREADS, 1, 1);
        dim3 grid(NT / (2 * THREADS), BQ / QT, 1);
        cost_kernel<<<grid, block>>>(pred_boxes, tgt_labels, tgt_boxes, out);
    }
}